// round 7
// baseline (speedup 1.0000x reference)
#include <cuda_runtime.h>
#include <cuda_fp16.h>
#include <cstdint>

#define INV_SCALE 0.35355339059327373f
#define PT_CAP (1 << 20)
#define NB  512     // sort blocks
#define TPB 512     // threads per sort block

// Scratch (allocation-free: __device__ globals).
__device__ float  g_vol32[28 * 32 * 32 * 32];
__device__ float  g_vol64[28 * 64 * 64 * 64];
__device__ __half g_vol128h[128 * 128 * 128 * 28];   // channel-last fp16, 117MB
__device__ unsigned int g_bh[512 * NB];              // per-(bin,block) counts/bases
__device__ float4 g_sorted[PT_CAP];                  // xyz + orig index

// ---------------------------------------------------------------------------
// Inverse 3D Haar butterfly
// ---------------------------------------------------------------------------
__device__ __forceinline__ void haar_butterfly(
    float a, float d0, float d1, float d2, float d3, float d4, float d5, float d6,
    float o[2][2][2])
{
    float e000 = a  + d0, e001 = a  - d0;
    float e010 = d1 + d2, e011 = d1 - d2;
    float e100 = d3 + d4, e101 = d3 - d4;
    float e110 = d5 + d6, e111 = d5 - d6;
    float f000 = e000 + e010, f010 = e000 - e010;
    float f001 = e001 + e011, f011 = e001 - e011;
    float f100 = e100 + e110, f110 = e100 - e110;
    float f101 = e101 + e111, f111 = e101 - e111;
    o[0][0][0] = (f000 + f100) * INV_SCALE;
    o[0][0][1] = (f001 + f101) * INV_SCALE;
    o[0][1][0] = (f010 + f110) * INV_SCALE;
    o[0][1][1] = (f011 + f111) * INV_SCALE;
    o[1][0][0] = (f000 - f100) * INV_SCALE;
    o[1][0][1] = (f001 - f101) * INV_SCALE;
    o[1][1][0] = (f010 - f110) * INV_SCALE;
    o[1][1][1] = (f011 - f111) * INV_SCALE;
}

// ---------------------------------------------------------------------------
// Levels 0 and 1: channel-major fp32 in/out.
// ---------------------------------------------------------------------------
template <int D>
__global__ void idwt_cm_kernel(const float* __restrict__ approx,
                               const float* __restrict__ det,
                               float* __restrict__ out)
{
    const int D3 = D * D * D;
    int tid = blockIdx.x * blockDim.x + threadIdx.x;
    if (tid >= 28 * D3) return;

    int k = tid % D;
    int j = (tid / D) % D;
    int i = (tid / (D * D)) % D;
    int c = tid / D3;
    int sp = (i * D + j) * D + k;

    float a  = __ldg(&approx[c * D3 + sp]);
    float d0 = __ldg(&det[(0 * 28 + c) * D3 + sp]);
    float d1 = __ldg(&det[(1 * 28 + c) * D3 + sp]);
    float d2 = __ldg(&det[(2 * 28 + c) * D3 + sp]);
    float d3 = __ldg(&det[(3 * 28 + c) * D3 + sp]);
    float d4 = __ldg(&det[(4 * 28 + c) * D3 + sp]);
    float d5 = __ldg(&det[(5 * 28 + c) * D3 + sp]);
    float d6 = __ldg(&det[(6 * 28 + c) * D3 + sp]);

    float o[2][2][2];
    haar_butterfly(a, d0, d1, d2, d3, d4, d5, d6, o);

    const int E = 2 * D;
#pragma unroll
    for (int p = 0; p < 2; ++p)
#pragma unroll
        for (int q = 0; q < 2; ++q) {
            int base = ((c * E + (2 * i + p)) * E + (2 * j + q)) * E + 2 * k;
            *reinterpret_cast<float2*>(&out[base]) =
                make_float2(o[p][q][0], o[p][q][1]);
        }
}

// ---------------------------------------------------------------------------
// Level 2: channel-major 64^3 fp32 -> channel-last 128^3 fp16 via smem.
// ---------------------------------------------------------------------------
__global__ __launch_bounds__(896) void idwt2_kernel(const float* __restrict__ det)
{
    const int D = 64, D3 = D * D * D;
    int ij = blockIdx.x;
    int i = ij / 64;
    int j = ij % 64;
    int c  = threadIdx.x / 32;
    int kl = threadIdx.x % 32;

    __shared__ float sm[4][64 * 29];

    for (int h = 0; h < 2; ++h) {
        int k  = kl + 32 * h;
        int sp = (i * D + j) * D + k;

        float a  = __ldcs(&g_vol64[c * D3 + sp]);
        float d0 = __ldcs(&det[(0 * 28 + c) * D3 + sp]);
        float d1 = __ldcs(&det[(1 * 28 + c) * D3 + sp]);
        float d2 = __ldcs(&det[(2 * 28 + c) * D3 + sp]);
        float d3 = __ldcs(&det[(3 * 28 + c) * D3 + sp]);
        float d4 = __ldcs(&det[(4 * 28 + c) * D3 + sp]);
        float d5 = __ldcs(&det[(5 * 28 + c) * D3 + sp]);
        float d6 = __ldcs(&det[(6 * 28 + c) * D3 + sp]);

        float o[2][2][2];
        haar_butterfly(a, d0, d1, d2, d3, d4, d5, d6, o);

#pragma unroll
        for (int p = 0; p < 2; ++p)
#pragma unroll
            for (int q = 0; q < 2; ++q)
#pragma unroll
                for (int r = 0; r < 2; ++r)
                    sm[p * 2 + q][(2 * kl + r) * 29 + c] = o[p][q][r];

        __syncthreads();

        __half2* vol2 = reinterpret_cast<__half2*>(g_vol128h);
        for (int idx = threadIdx.x; idx < 4 * 64 * 14; idx += 896) {
            int pq   = idx / (64 * 14);
            int rem2 = idx % (64 * 14);
            int x    = rem2 / 14;
            int m    = rem2 % 14;
            int p = pq >> 1, q = pq & 1;
            float lo = sm[pq][x * 29 + 2 * m];
            float hi = sm[pq][x * 29 + 2 * m + 1];
            int base2 = ((((2 * i + p) * 128 + (2 * j + q)) * 128 + 64 * h) * 14);
            vol2[base2 + rem2] = __floats2half2_rn(lo, hi);
        }
        __syncthreads();
    }
}

// ---------------------------------------------------------------------------
// Spatial binning: 8x8x8 = 512 tiles of 16^3 voxels.
// ---------------------------------------------------------------------------
__device__ __forceinline__ int point_bin(float x, float y, float z)
{
    const float S = 127.0f / 3.0f;
    int x0 = (int)floorf(fmaf(x, S, 63.5f));
    int y0 = (int)floorf(fmaf(y, S, 63.5f));
    int z0 = (int)floorf(fmaf(z, S, 63.5f));
    x0 = min(max(x0, 0), 127);
    y0 = min(max(y0, 0), 127);
    z0 = min(max(z0, 0), 127);
    return ((z0 >> 4) << 6) | ((y0 >> 4) << 3) | (x0 >> 4);
}

// Pass 1: per-block shared-memory histogram -> g_bh[bin*NB + block]
__global__ __launch_bounds__(TPB) void hist_kernel(const float* __restrict__ xyz,
                                                   int n, int chunk)
{
    __shared__ unsigned int h[512];
    for (int i = threadIdx.x; i < 512; i += TPB) h[i] = 0;
    __syncthreads();

    int start = blockIdx.x * chunk;
    int end   = min(start + chunk, n);
    for (int p = start + threadIdx.x; p < end; p += TPB) {
        float x = __ldcs(&xyz[3 * p + 0]);
        float y = __ldcs(&xyz[3 * p + 1]);
        float z = __ldcs(&xyz[3 * p + 2]);
        atomicAdd(&h[point_bin(x, y, z)], 1u);
    }
    __syncthreads();
    for (int i = threadIdx.x; i < 512; i += TPB)
        g_bh[i * NB + blockIdx.x] = h[i];
}

// Scan: one block, 512 threads (one per bin). Converts counts -> exclusive
// bases in bin-major-then-block order.
__global__ __launch_bounds__(512) void scan_kernel()
{
    int b = threadIdx.x;
    unsigned int sum = 0;
    for (int k = 0; k < NB; ++k) sum += g_bh[b * NB + k];

    __shared__ unsigned int s[512];
    s[b] = sum;
    __syncthreads();
    for (int d = 1; d < 512; d <<= 1) {
        unsigned int v = (b >= d) ? s[b - d] : 0u;
        __syncthreads();
        s[b] += v;
        __syncthreads();
    }
    unsigned int base = s[b] - sum;   // exclusive over bins
    for (int k = 0; k < NB; ++k) {
        unsigned int c = g_bh[b * NB + k];
        g_bh[b * NB + k] = base;
        base += c;
    }
}

// Pass 2: scatter into pre-reserved per-(bin,block) slots; smem atomics only.
__global__ __launch_bounds__(TPB) void scatter_kernel(const float* __restrict__ xyz,
                                                      int n, int chunk)
{
    __shared__ unsigned int h[512];
    for (int i = threadIdx.x; i < 512; i += TPB)
        h[i] = g_bh[i * NB + blockIdx.x];
    __syncthreads();

    int start = blockIdx.x * chunk;
    int end   = min(start + chunk, n);
    for (int p = start + threadIdx.x; p < end; p += TPB) {
        float x = __ldcs(&xyz[3 * p + 0]);
        float y = __ldcs(&xyz[3 * p + 1]);
        float z = __ldcs(&xyz[3 * p + 2]);
        unsigned int pos = atomicAdd(&h[point_bin(x, y, z)], 1u);
        g_sorted[pos] = make_float4(x, y, z, __int_as_float(p));
    }
}

// ---------------------------------------------------------------------------
// Sampling over spatially-sorted points: 2 points per warp, lane = channel
// pair (half2). Output written to the point's ORIGINAL row.
// ---------------------------------------------------------------------------
__global__ void sample_sorted_kernel(float* __restrict__ out, int n)
{
    int warp   = (blockIdx.x * blockDim.x + threadIdx.x) >> 5;
    int lane   = threadIdx.x & 31;
    int sub    = lane >> 4;
    int lane14 = lane & 15;
    int sp     = warp * 2 + sub;
    if (sp >= n || lane14 >= 14) return;

    float4 pt = __ldg(&g_sorted[sp]);
    int orig = __float_as_int(pt.w);

    const float S = 127.0f / 3.0f;
    float px = fmaf(pt.x, S, 63.5f);
    float py = fmaf(pt.y, S, 63.5f);
    float pz = fmaf(pt.z, S, 63.5f);

    float flx = floorf(px), fly = floorf(py), flz = floorf(pz);
    int x0 = (int)flx, y0 = (int)fly, z0 = (int)flz;
    float fx = px - flx, fy = py - fly, fz = pz - flz;

    float wx[2] = {1.0f - fx, fx};
    float wy[2] = {1.0f - fy, fy};
    float wz[2] = {1.0f - fz, fz};

    const __half2* __restrict__ vol2 =
        reinterpret_cast<const __half2*>(g_vol128h);

    float accx = 0.0f, accy = 0.0f;

#pragma unroll
    for (int dz = 0; dz < 2; ++dz) {
        int iz = z0 + dz;
        bool vz = (iz >= 0) & (iz < 128);
#pragma unroll
        for (int dy = 0; dy < 2; ++dy) {
            int iy = y0 + dy;
            bool vy = (iy >= 0) & (iy < 128);
#pragma unroll
            for (int dx = 0; dx < 2; ++dx) {
                int ix = x0 + dx;
                bool vx = (ix >= 0) & (ix < 128);
                if (vx & vy & vz) {
                    float wgt = wx[dx] * wy[dy] * wz[dz];
                    int idx = ((iz * 128 + iy) * 128 + ix) * 14 + lane14;
                    float2 f = __half22float2(vol2[idx]);
                    accx = fmaf(wgt, f.x, accx);
                    accy = fmaf(wgt, f.y, accy);
                }
            }
        }
    }

    __stwt(reinterpret_cast<float2*>(&out[(size_t)orig * 28 + 2 * lane14]),
           make_float2(accx, accy));
}

// Fallback (unsorted) for n > PT_CAP — identical math, original order.
__global__ void sample_kernel(const float* __restrict__ xyz,
                              float* __restrict__ out, int n)
{
    int warp   = (blockIdx.x * blockDim.x + threadIdx.x) >> 5;
    int lane   = threadIdx.x & 31;
    int sub    = lane >> 4;
    int lane14 = lane & 15;
    int p      = warp * 2 + sub;
    if (p >= n || lane14 >= 14) return;

    float x = __ldcs(&xyz[3 * p + 0]);
    float y = __ldcs(&xyz[3 * p + 1]);
    float z = __ldcs(&xyz[3 * p + 2]);

    const float S = 127.0f / 3.0f;
    float px = fmaf(x, S, 63.5f);
    float py = fmaf(y, S, 63.5f);
    float pz = fmaf(z, S, 63.5f);

    float flx = floorf(px), fly = floorf(py), flz = floorf(pz);
    int x0 = (int)flx, y0 = (int)fly, z0 = (int)flz;
    float fx = px - flx, fy = py - fly, fz = pz - flz;

    float wx[2] = {1.0f - fx, fx};
    float wy[2] = {1.0f - fy, fy};
    float wz[2] = {1.0f - fz, fz};

    const __half2* __restrict__ vol2 =
        reinterpret_cast<const __half2*>(g_vol128h);

    float accx = 0.0f, accy = 0.0f;

#pragma unroll
    for (int dz = 0; dz < 2; ++dz) {
        int iz = z0 + dz;
        bool vz = (iz >= 0) & (iz < 128);
#pragma unroll
        for (int dy = 0; dy < 2; ++dy) {
            int iy = y0 + dy;
            bool vy = (iy >= 0) & (iy < 128);
#pragma unroll
            for (int dx = 0; dx < 2; ++dx) {
                int ix = x0 + dx;
                bool vx = (ix >= 0) & (ix < 128);
                if (vx & vy & vz) {
                    float wgt = wx[dx] * wy[dy] * wz[dz];
                    int idx = ((iz * 128 + iy) * 128 + ix) * 14 + lane14;
                    float2 f = __half22float2(vol2[idx]);
                    accx = fmaf(wgt, f.x, accx);
                    accy = fmaf(wgt, f.y, accy);
                }
            }
        }
    }

    __stwt(reinterpret_cast<float2*>(&out[(size_t)p * 28 + 2 * lane14]),
           make_float2(accx, accy));
}

// ---------------------------------------------------------------------------
extern "C" void kernel_launch(void* const* d_in, const int* in_sizes, int n_in,
                              void* d_out, int out_size)
{
    const float* approx    = (const float*)d_in[0];
    const float* details_0 = (const float*)d_in[1];
    const float* details_1 = (const float*)d_in[2];
    const float* details_2 = (const float*)d_in[3];
    const float* xyz       = (const float*)d_in[4];
    float* out             = (float*)d_out;

    int n = in_sizes[4] / 3;

    float* p32 = nullptr;
    float* p64 = nullptr;
    cudaGetSymbolAddress((void**)&p32, g_vol32);
    cudaGetSymbolAddress((void**)&p64, g_vol64);

    // Reconstruction
    {
        int nthreads = 28 * 16 * 16 * 16;
        idwt_cm_kernel<16><<<(nthreads + 255) / 256, 256>>>(approx, details_0, p32);
    }
    {
        int nthreads = 28 * 32 * 32 * 32;
        idwt_cm_kernel<32><<<(nthreads + 255) / 256, 256>>>(p32, details_1, p64);
    }
    idwt2_kernel<<<64 * 64, 896>>>(details_2);

    if (n <= PT_CAP) {
        int chunk = (n + NB - 1) / NB;
        hist_kernel<<<NB, TPB>>>(xyz, n, chunk);
        scan_kernel<<<1, 512>>>();
        scatter_kernel<<<NB, TPB>>>(xyz, n, chunk);
        int blocks = (n + 15) / 16;
        sample_sorted_kernel<<<blocks, 256>>>(out, n);
    } else {
        int blocks = (n + 15) / 16;
        sample_kernel<<<blocks, 256>>>(xyz, out, n);
    }
}

// round 8
// speedup vs baseline: 3.0548x; 3.0548x over previous
#include <cuda_runtime.h>
#include <cuda_fp16.h>
#include <cstdint>

#define INV_SCALE 0.35355339059327373f
#define PT_CAP (1 << 20)
#define NB  512     // sort blocks
#define TPB 512     // threads per sort block

// Scratch (allocation-free: __device__ globals).
__device__ float  g_vol32[28 * 32 * 32 * 32];
__device__ float  g_vol64[28 * 64 * 64 * 64];
__device__ __half g_vol128h[128 * 128 * 128 * 28];   // channel-last fp16, 117MB
__device__ unsigned int g_bh[512 * NB];              // per-(bin,block) counts -> row prefixes
__device__ unsigned int g_bintot[512];
__device__ unsigned int g_binbase[512];
__device__ float4 g_sorted[PT_CAP];                  // xyz + orig index

// ---------------------------------------------------------------------------
// Inverse 3D Haar butterfly
// ---------------------------------------------------------------------------
__device__ __forceinline__ void haar_butterfly(
    float a, float d0, float d1, float d2, float d3, float d4, float d5, float d6,
    float o[2][2][2])
{
    float e000 = a  + d0, e001 = a  - d0;
    float e010 = d1 + d2, e011 = d1 - d2;
    float e100 = d3 + d4, e101 = d3 - d4;
    float e110 = d5 + d6, e111 = d5 - d6;
    float f000 = e000 + e010, f010 = e000 - e010;
    float f001 = e001 + e011, f011 = e001 - e011;
    float f100 = e100 + e110, f110 = e100 - e110;
    float f101 = e101 + e111, f111 = e101 - e111;
    o[0][0][0] = (f000 + f100) * INV_SCALE;
    o[0][0][1] = (f001 + f101) * INV_SCALE;
    o[0][1][0] = (f010 + f110) * INV_SCALE;
    o[0][1][1] = (f011 + f111) * INV_SCALE;
    o[1][0][0] = (f000 - f100) * INV_SCALE;
    o[1][0][1] = (f001 - f101) * INV_SCALE;
    o[1][1][0] = (f010 - f110) * INV_SCALE;
    o[1][1][1] = (f011 - f111) * INV_SCALE;
}

// ---------------------------------------------------------------------------
// Levels 0 and 1: channel-major fp32 in/out.
// ---------------------------------------------------------------------------
template <int D>
__global__ void idwt_cm_kernel(const float* __restrict__ approx,
                               const float* __restrict__ det,
                               float* __restrict__ out)
{
    const int D3 = D * D * D;
    int tid = blockIdx.x * blockDim.x + threadIdx.x;
    if (tid >= 28 * D3) return;

    int k = tid % D;
    int j = (tid / D) % D;
    int i = (tid / (D * D)) % D;
    int c = tid / D3;
    int sp = (i * D + j) * D + k;

    float a  = __ldg(&approx[c * D3 + sp]);
    float d0 = __ldg(&det[(0 * 28 + c) * D3 + sp]);
    float d1 = __ldg(&det[(1 * 28 + c) * D3 + sp]);
    float d2 = __ldg(&det[(2 * 28 + c) * D3 + sp]);
    float d3 = __ldg(&det[(3 * 28 + c) * D3 + sp]);
    float d4 = __ldg(&det[(4 * 28 + c) * D3 + sp]);
    float d5 = __ldg(&det[(5 * 28 + c) * D3 + sp]);
    float d6 = __ldg(&det[(6 * 28 + c) * D3 + sp]);

    float o[2][2][2];
    haar_butterfly(a, d0, d1, d2, d3, d4, d5, d6, o);

    const int E = 2 * D;
#pragma unroll
    for (int p = 0; p < 2; ++p)
#pragma unroll
        for (int q = 0; q < 2; ++q) {
            int base = ((c * E + (2 * i + p)) * E + (2 * j + q)) * E + 2 * k;
            *reinterpret_cast<float2*>(&out[base]) =
                make_float2(o[p][q][0], o[p][q][1]);
        }
}

// ---------------------------------------------------------------------------
// Level 2: channel-major 64^3 fp32 -> channel-last 128^3 fp16 via smem.
// ---------------------------------------------------------------------------
__global__ __launch_bounds__(896) void idwt2_kernel(const float* __restrict__ det)
{
    const int D = 64, D3 = D * D * D;
    int ij = blockIdx.x;
    int i = ij / 64;
    int j = ij % 64;
    int c  = threadIdx.x / 32;
    int kl = threadIdx.x % 32;

    __shared__ float sm[4][64 * 29];

    for (int h = 0; h < 2; ++h) {
        int k  = kl + 32 * h;
        int sp = (i * D + j) * D + k;

        float a  = __ldcs(&g_vol64[c * D3 + sp]);
        float d0 = __ldcs(&det[(0 * 28 + c) * D3 + sp]);
        float d1 = __ldcs(&det[(1 * 28 + c) * D3 + sp]);
        float d2 = __ldcs(&det[(2 * 28 + c) * D3 + sp]);
        float d3 = __ldcs(&det[(3 * 28 + c) * D3 + sp]);
        float d4 = __ldcs(&det[(4 * 28 + c) * D3 + sp]);
        float d5 = __ldcs(&det[(5 * 28 + c) * D3 + sp]);
        float d6 = __ldcs(&det[(6 * 28 + c) * D3 + sp]);

        float o[2][2][2];
        haar_butterfly(a, d0, d1, d2, d3, d4, d5, d6, o);

#pragma unroll
        for (int p = 0; p < 2; ++p)
#pragma unroll
            for (int q = 0; q < 2; ++q)
#pragma unroll
                for (int r = 0; r < 2; ++r)
                    sm[p * 2 + q][(2 * kl + r) * 29 + c] = o[p][q][r];

        __syncthreads();

        __half2* vol2 = reinterpret_cast<__half2*>(g_vol128h);
        for (int idx = threadIdx.x; idx < 4 * 64 * 14; idx += 896) {
            int pq   = idx / (64 * 14);
            int rem2 = idx % (64 * 14);
            int x    = rem2 / 14;
            int m    = rem2 % 14;
            int p = pq >> 1, q = pq & 1;
            float lo = sm[pq][x * 29 + 2 * m];
            float hi = sm[pq][x * 29 + 2 * m + 1];
            int base2 = ((((2 * i + p) * 128 + (2 * j + q)) * 128 + 64 * h) * 14);
            vol2[base2 + rem2] = __floats2half2_rn(lo, hi);
        }
        __syncthreads();
    }
}

// ---------------------------------------------------------------------------
// Spatial binning: 8x8x8 = 512 tiles of 16^3 voxels.
// ---------------------------------------------------------------------------
__device__ __forceinline__ int point_bin(float x, float y, float z)
{
    const float S = 127.0f / 3.0f;
    int x0 = (int)floorf(fmaf(x, S, 63.5f));
    int y0 = (int)floorf(fmaf(y, S, 63.5f));
    int z0 = (int)floorf(fmaf(z, S, 63.5f));
    x0 = min(max(x0, 0), 127);
    y0 = min(max(y0, 0), 127);
    z0 = min(max(z0, 0), 127);
    return ((z0 >> 4) << 6) | ((y0 >> 4) << 3) | (x0 >> 4);
}

// Pass 1: per-block shared-memory histogram -> g_bh[bin*NB + block]
__global__ __launch_bounds__(TPB) void hist_kernel(const float* __restrict__ xyz,
                                                   int n, int chunk)
{
    __shared__ unsigned int h[512];
    for (int i = threadIdx.x; i < 512; i += TPB) h[i] = 0;
    __syncthreads();

    int start = blockIdx.x * chunk;
    int end   = min(start + chunk, n);
    for (int p = start + threadIdx.x; p < end; p += TPB) {
        float x = __ldcs(&xyz[3 * p + 0]);
        float y = __ldcs(&xyz[3 * p + 1]);
        float z = __ldcs(&xyz[3 * p + 2]);
        atomicAdd(&h[point_bin(x, y, z)], 1u);
    }
    __syncthreads();
    for (int i = threadIdx.x; i < 512; i += TPB)
        g_bh[i * NB + blockIdx.x] = h[i];
}

// Scan stage A: one block per bin. Exclusive prefix within the bin's row
// (coalesced), row total -> g_bintot[bin].
__global__ __launch_bounds__(NB) void scan_rows_kernel()
{
    __shared__ unsigned int s[NB];
    int bin = blockIdx.x;
    int t = threadIdx.x;
    unsigned int own = g_bh[bin * NB + t];
    s[t] = own;
    __syncthreads();
    for (int d = 1; d < NB; d <<= 1) {
        unsigned int v = (t >= d) ? s[t - d] : 0u;
        __syncthreads();
        s[t] += v;
        __syncthreads();
    }
    g_bh[bin * NB + t] = s[t] - own;        // exclusive within row
    if (t == NB - 1) g_bintot[bin] = s[t];  // row total
}

// Scan stage B: one block, exclusive scan over 512 bin totals.
__global__ __launch_bounds__(512) void scan_bins_kernel()
{
    __shared__ unsigned int s[512];
    int t = threadIdx.x;
    unsigned int own = g_bintot[t];
    s[t] = own;
    __syncthreads();
    for (int d = 1; d < 512; d <<= 1) {
        unsigned int v = (t >= d) ? s[t - d] : 0u;
        __syncthreads();
        s[t] += v;
        __syncthreads();
    }
    g_binbase[t] = s[t] - own;
}

// Pass 2: scatter into pre-reserved per-(bin,block) slots; smem atomics only.
__global__ __launch_bounds__(TPB) void scatter_kernel(const float* __restrict__ xyz,
                                                      int n, int chunk)
{
    __shared__ unsigned int h[512];
    for (int i = threadIdx.x; i < 512; i += TPB)
        h[i] = g_bh[i * NB + blockIdx.x] + g_binbase[i];
    __syncthreads();

    int start = blockIdx.x * chunk;
    int end   = min(start + chunk, n);
    for (int p = start + threadIdx.x; p < end; p += TPB) {
        float x = __ldcs(&xyz[3 * p + 0]);
        float y = __ldcs(&xyz[3 * p + 1]);
        float z = __ldcs(&xyz[3 * p + 2]);
        unsigned int pos = atomicAdd(&h[point_bin(x, y, z)], 1u);
        g_sorted[pos] = make_float4(x, y, z, __int_as_float(p));
    }
}

// ---------------------------------------------------------------------------
// Sampling over spatially-sorted points: 2 points per warp, lane = channel
// pair (half2). Output written to the point's ORIGINAL row.
// ---------------------------------------------------------------------------
__global__ void sample_sorted_kernel(float* __restrict__ out, int n)
{
    int warp   = (blockIdx.x * blockDim.x + threadIdx.x) >> 5;
    int lane   = threadIdx.x & 31;
    int sub    = lane >> 4;
    int lane14 = lane & 15;
    int sp     = warp * 2 + sub;
    if (sp >= n || lane14 >= 14) return;

    float4 pt = __ldg(&g_sorted[sp]);
    int orig = __float_as_int(pt.w);

    const float S = 127.0f / 3.0f;
    float px = fmaf(pt.x, S, 63.5f);
    float py = fmaf(pt.y, S, 63.5f);
    float pz = fmaf(pt.z, S, 63.5f);

    float flx = floorf(px), fly = floorf(py), flz = floorf(pz);
    int x0 = (int)flx, y0 = (int)fly, z0 = (int)flz;
    float fx = px - flx, fy = py - fly, fz = pz - flz;

    float wx[2] = {1.0f - fx, fx};
    float wy[2] = {1.0f - fy, fy};
    float wz[2] = {1.0f - fz, fz};

    const __half2* __restrict__ vol2 =
        reinterpret_cast<const __half2*>(g_vol128h);

    float accx = 0.0f, accy = 0.0f;

#pragma unroll
    for (int dz = 0; dz < 2; ++dz) {
        int iz = z0 + dz;
        bool vz = (iz >= 0) & (iz < 128);
#pragma unroll
        for (int dy = 0; dy < 2; ++dy) {
            int iy = y0 + dy;
            bool vy = (iy >= 0) & (iy < 128);
#pragma unroll
            for (int dx = 0; dx < 2; ++dx) {
                int ix = x0 + dx;
                bool vx = (ix >= 0) & (ix < 128);
                if (vx & vy & vz) {
                    float wgt = wx[dx] * wy[dy] * wz[dz];
                    int idx = ((iz * 128 + iy) * 128 + ix) * 14 + lane14;
                    float2 f = __half22float2(vol2[idx]);
                    accx = fmaf(wgt, f.x, accx);
                    accy = fmaf(wgt, f.y, accy);
                }
            }
        }
    }

    __stwt(reinterpret_cast<float2*>(&out[(size_t)orig * 28 + 2 * lane14]),
           make_float2(accx, accy));
}

// Fallback (unsorted) for n > PT_CAP — identical math, original order.
__global__ void sample_kernel(const float* __restrict__ xyz,
                              float* __restrict__ out, int n)
{
    int warp   = (blockIdx.x * blockDim.x + threadIdx.x) >> 5;
    int lane   = threadIdx.x & 31;
    int sub    = lane >> 4;
    int lane14 = lane & 15;
    int p      = warp * 2 + sub;
    if (p >= n || lane14 >= 14) return;

    float x = __ldcs(&xyz[3 * p + 0]);
    float y = __ldcs(&xyz[3 * p + 1]);
    float z = __ldcs(&xyz[3 * p + 2]);

    const float S = 127.0f / 3.0f;
    float px = fmaf(x, S, 63.5f);
    float py = fmaf(y, S, 63.5f);
    float pz = fmaf(z, S, 63.5f);

    float flx = floorf(px), fly = floorf(py), flz = floorf(pz);
    int x0 = (int)flx, y0 = (int)fly, z0 = (int)flz;
    float fx = px - flx, fy = py - fly, fz = pz - flz;

    float wx[2] = {1.0f - fx, fx};
    float wy[2] = {1.0f - fy, fy};
    float wz[2] = {1.0f - fz, fz};

    const __half2* __restrict__ vol2 =
        reinterpret_cast<const __half2*>(g_vol128h);

    float accx = 0.0f, accy = 0.0f;

#pragma unroll
    for (int dz = 0; dz < 2; ++dz) {
        int iz = z0 + dz;
        bool vz = (iz >= 0) & (iz < 128);
#pragma unroll
        for (int dy = 0; dy < 2; ++dy) {
            int iy = y0 + dy;
            bool vy = (iy >= 0) & (iy < 128);
#pragma unroll
            for (int dx = 0; dx < 2; ++dx) {
                int ix = x0 + dx;
                bool vx = (ix >= 0) & (ix < 128);
                if (vx & vy & vz) {
                    float wgt = wx[dx] * wy[dy] * wz[dz];
                    int idx = ((iz * 128 + iy) * 128 + ix) * 14 + lane14;
                    float2 f = __half22float2(vol2[idx]);
                    accx = fmaf(wgt, f.x, accx);
                    accy = fmaf(wgt, f.y, accy);
                }
            }
        }
    }

    __stwt(reinterpret_cast<float2*>(&out[(size_t)p * 28 + 2 * lane14]),
           make_float2(accx, accy));
}

// ---------------------------------------------------------------------------
extern "C" void kernel_launch(void* const* d_in, const int* in_sizes, int n_in,
                              void* d_out, int out_size)
{
    const float* approx    = (const float*)d_in[0];
    const float* details_0 = (const float*)d_in[1];
    const float* details_1 = (const float*)d_in[2];
    const float* details_2 = (const float*)d_in[3];
    const float* xyz       = (const float*)d_in[4];
    float* out             = (float*)d_out;

    int n = in_sizes[4] / 3;

    float* p32 = nullptr;
    float* p64 = nullptr;
    cudaGetSymbolAddress((void**)&p32, g_vol32);
    cudaGetSymbolAddress((void**)&p64, g_vol64);

    // Reconstruction
    {
        int nthreads = 28 * 16 * 16 * 16;
        idwt_cm_kernel<16><<<(nthreads + 255) / 256, 256>>>(approx, details_0, p32);
    }
    {
        int nthreads = 28 * 32 * 32 * 32;
        idwt_cm_kernel<32><<<(nthreads + 255) / 256, 256>>>(p32, details_1, p64);
    }
    idwt2_kernel<<<64 * 64, 896>>>(details_2);

    if (n <= PT_CAP) {
        int chunk = (n + NB - 1) / NB;
        hist_kernel<<<NB, TPB>>>(xyz, n, chunk);
        scan_rows_kernel<<<512, NB>>>();
        scan_bins_kernel<<<1, 512>>>();
        scatter_kernel<<<NB, TPB>>>(xyz, n, chunk);
        int blocks = (n + 15) / 16;
        sample_sorted_kernel<<<blocks, 256>>>(out, n);
    } else {
        int blocks = (n + 15) / 16;
        sample_kernel<<<blocks, 256>>>(xyz, out, n);
    }
}